// round 2
// baseline (speedup 1.0000x reference)
#include <cuda_runtime.h>
#include <cuda_bf16.h>

#define BB 16
#define HH 56
#define WWI 56
#define CC 512
#define NHEADS 16
#define DH 32
#define NTOK 49
#define SHIFTV 3
#define NWIN 1024            // B * 64 windows
#define MTOT (NWIN * NTOK)   // 50176
#define NQKV 1536
#define QKV_STRIDE (NWIN * NHEADS * NTOK * DH)   // 25690112 elements per q/k/v plane

// Scratch (device globals; no allocations allowed)
__device__ float g_qkv[3 * QKV_STRIDE];   // [which][win][head][tok][d]
__device__ float g_ao[MTOT * CC];

// ---------------------------------------------------------------------------
// GEMM tiling: 128 x 64 x 16, 256 threads, 8x4 microtile per thread
// ---------------------------------------------------------------------------
#define BM1 128
#define BN1 64
#define BK1 16

// QKV GEMM: A = window-partitioned shifted x (gathered), B = qkv_w [512,1536].
// Epilogue scatters into g_qkv (q pre-scaled) with [which][win][head][tok][d] layout.
__global__ __launch_bounds__(256) void qkv_kernel(
    const float* __restrict__ x,
    const float* __restrict__ qkv_w,
    const float* __restrict__ qkv_b)
{
    __shared__ float As[BK1][BM1];
    __shared__ float Bs[BK1][BN1];
    __shared__ int rowBase[BM1];

    const int tid = threadIdx.x;
    const int bm = blockIdx.x * BM1;
    const int bn = blockIdx.y * BN1;

    if (tid < BM1) {
        int m = bm + tid;
        int win = m / NTOK, token = m - win * NTOK;
        int b = win >> 6, widx = win & 63;
        int wh = widx >> 3, ww = widx & 7;
        int th = token / 7, tw = token - th * 7;
        int h = wh * 7 + th + SHIFTV; if (h >= HH)  h -= HH;
        int w = ww * 7 + tw + SHIFTV; if (w >= WWI) w -= WWI;
        rowBase[tid] = ((b * HH + h) * WWI + w) * CC;
    }
    __syncthreads();

    const int arow = tid >> 2;          // 0..63
    const int acol = (tid & 3) * 4;
    const int rb0 = rowBase[arow];
    const int rb1 = rowBase[arow + 64];
    const int brow = tid >> 4;          // 0..15
    const int bcol = (tid & 15) * 4;
    const int tx = tid & 15, ty = tid >> 4;

    float acc[8][4];
    #pragma unroll
    for (int i = 0; i < 8; i++)
        #pragma unroll
        for (int j = 0; j < 4; j++) acc[i][j] = 0.f;

    for (int k0 = 0; k0 < CC; k0 += BK1) {
        float4 a0 = *(const float4*)(x + rb0 + k0 + acol);
        float4 a1 = *(const float4*)(x + rb1 + k0 + acol);
        As[acol + 0][arow] = a0.x; As[acol + 1][arow] = a0.y;
        As[acol + 2][arow] = a0.z; As[acol + 3][arow] = a0.w;
        As[acol + 0][arow + 64] = a1.x; As[acol + 1][arow + 64] = a1.y;
        As[acol + 2][arow + 64] = a1.z; As[acol + 3][arow + 64] = a1.w;
        *(float4*)&Bs[brow][bcol] =
            *(const float4*)(qkv_w + (k0 + brow) * NQKV + bn + bcol);
        __syncthreads();
        #pragma unroll
        for (int kk = 0; kk < BK1; kk++) {
            float4 b4  = *(const float4*)&Bs[kk][tx * 4];
            float4 a4a = *(const float4*)&As[kk][ty * 8];
            float4 a4b = *(const float4*)&As[kk][ty * 8 + 4];
            float ar[8] = {a4a.x, a4a.y, a4a.z, a4a.w, a4b.x, a4b.y, a4b.z, a4b.w};
            float br[4] = {b4.x, b4.y, b4.z, b4.w};
            #pragma unroll
            for (int i = 0; i < 8; i++)
                #pragma unroll
                for (int j = 0; j < 4; j++) acc[i][j] += ar[i] * br[j];
        }
        __syncthreads();
    }

    const float scale = 0.17677669529663687f;   // 32^-0.5
    // decode row 0 of the microtile once, then step token/win incrementally
    int m0 = bm + ty * 8;
    int win = m0 / NTOK, token = m0 - win * NTOK;
    #pragma unroll
    for (int i = 0; i < 8; i++) {
        #pragma unroll
        for (int j = 0; j < 4; j++) {
            int n = bn + tx * 4 + j;
            float val = acc[i][j] + qkv_b[n];
            int which = n >> 9;
            int head = (n >> 5) & 15;
            int dim = n & 31;
            if (which == 0) val *= scale;
            g_qkv[which * QKV_STRIDE +
                  ((win * NHEADS + head) * NTOK + token) * DH + dim] = val;
        }
        token++; if (token == NTOK) { token = 0; win++; }
    }
}

// ---------------------------------------------------------------------------
// Fused attention: one block per (window, head). S = qK^T + bias + mask,
// softmax, O = P V. Bias index & shift mask computed analytically.
// ---------------------------------------------------------------------------
__global__ __launch_bounds__(256) void attn_kernel(const float* __restrict__ bias_table)
{
    __shared__ float q_s[NTOK * DH];
    __shared__ float kT[DH * NTOK];
    __shared__ float v_s[NTOK * DH];
    __shared__ float S[NTOK * NTOK];
    __shared__ float biasH[169];
    __shared__ int reg_s[NTOK];

    const int tid = threadIdx.x;
    const int whid = blockIdx.x;          // win*16 + head
    const int win = whid >> 4;
    const int head = whid & 15;
    const int base = whid * (NTOK * DH);

    for (int idx = tid; idx < NTOK * DH; idx += 256) {
        q_s[idx] = g_qkv[base + idx];
        v_s[idx] = g_qkv[2 * QKV_STRIDE + base + idx];
        float kv = g_qkv[QKV_STRIDE + base + idx];
        int tok = idx >> 5, dim = idx & 31;
        kT[dim * NTOK + tok] = kv;        // stride 49 ≡ 17 mod 32 -> no conflicts
    }
    if (tid < 169) biasH[tid] = bias_table[tid * NHEADS + head];

    const int widx = win & 63;
    const int wh = widx >> 3, ww = widx & 7;
    const bool masked = (wh == 7) || (ww == 7);
    if (tid < NTOK) {
        int th = tid / 7, tw = tid - th * 7;
        int hs = wh * 7 + th, wsc = ww * 7 + tw;
        int rh = hs < 49 ? 0 : (hs < 53 ? 1 : 2);
        int rw = wsc < 49 ? 0 : (wsc < 53 ? 1 : 2);
        reg_s[tid] = rh * 3 + rw;
    }
    __syncthreads();

    for (int p = tid; p < NTOK * NTOK; p += 256) {
        int i = p / NTOK, j = p - i * NTOK;
        float s = 0.f;
        #pragma unroll
        for (int t = 0; t < DH; t++) s += q_s[i * DH + t] * kT[t * NTOK + j];
        int ri = i / 7, ci = i - ri * 7;
        int rj = j / 7, cj = j - rj * 7;
        s += biasH[(ri - rj + 6) * 13 + (ci - cj + 6)];
        if (masked && reg_s[i] != reg_s[j]) s -= 100.f;
        S[p] = s;
    }
    __syncthreads();

    const int lane = tid & 31, warp = tid >> 5;
    for (int i = warp; i < NTOK; i += 8) {
        float v1 = (lane < NTOK) ? S[i * NTOK + lane] : -1e30f;
        float v2 = (lane + 32 < NTOK) ? S[i * NTOK + lane + 32] : -1e30f;
        float m = fmaxf(v1, v2);
        #pragma unroll
        for (int o = 16; o > 0; o >>= 1) m = fmaxf(m, __shfl_xor_sync(0xffffffffu, m, o));
        float e1 = (lane < NTOK) ? __expf(v1 - m) : 0.f;
        float e2 = (lane + 32 < NTOK) ? __expf(v2 - m) : 0.f;
        float sum = e1 + e2;
        #pragma unroll
        for (int o = 16; o > 0; o >>= 1) sum += __shfl_xor_sync(0xffffffffu, sum, o);
        float inv = 1.f / sum;
        if (lane < NTOK) S[i * NTOK + lane] = e1 * inv;
        if (lane + 32 < NTOK) S[i * NTOK + lane + 32] = e2 * inv;
    }
    __syncthreads();

    const int outbase = (win * NTOK) * CC + head * DH;
    for (int p = tid; p < NTOK * DH; p += 256) {
        int i = p >> 5, dim = p & 31;
        float o = 0.f;
        #pragma unroll
        for (int j = 0; j < NTOK; j++) o += S[i * NTOK + j] * v_s[j * DH + dim];
        g_ao[outbase + i * CC + dim] = o;
    }
}

// ---------------------------------------------------------------------------
// Proj GEMM + bias + window-reverse + inverse cyclic shift + residual add
// ---------------------------------------------------------------------------
__global__ __launch_bounds__(256) void proj_kernel(
    const float* __restrict__ x,
    const float* __restrict__ proj_w,
    const float* __restrict__ proj_b,
    float* __restrict__ out)
{
    __shared__ float As[BK1][BM1];
    __shared__ float Bs[BK1][BN1];

    const int tid = threadIdx.x;
    const int bm = blockIdx.x * BM1;
    const int bn = blockIdx.y * BN1;

    const int arow = tid >> 2;
    const int acol = (tid & 3) * 4;
    const int brow = tid >> 4;
    const int bcol = (tid & 15) * 4;
    const int tx = tid & 15, ty = tid >> 4;

    const float* A = g_ao;

    float acc[8][4];
    #pragma unroll
    for (int i = 0; i < 8; i++)
        #pragma unroll
        for (int j = 0; j < 4; j++) acc[i][j] = 0.f;

    for (int k0 = 0; k0 < CC; k0 += BK1) {
        float4 a0 = *(const float4*)(A + (bm + arow) * CC + k0 + acol);
        float4 a1 = *(const float4*)(A + (bm + arow + 64) * CC + k0 + acol);
        As[acol + 0][arow] = a0.x; As[acol + 1][arow] = a0.y;
        As[acol + 2][arow] = a0.z; As[acol + 3][arow] = a0.w;
        As[acol + 0][arow + 64] = a1.x; As[acol + 1][arow + 64] = a1.y;
        As[acol + 2][arow + 64] = a1.z; As[acol + 3][arow + 64] = a1.w;
        *(float4*)&Bs[brow][bcol] =
            *(const float4*)(proj_w + (k0 + brow) * CC + bn + bcol);
        __syncthreads();
        #pragma unroll
        for (int kk = 0; kk < BK1; kk++) {
            float4 b4  = *(const float4*)&Bs[kk][tx * 4];
            float4 a4a = *(const float4*)&As[kk][ty * 8];
            float4 a4b = *(const float4*)&As[kk][ty * 8 + 4];
            float ar[8] = {a4a.x, a4a.y, a4a.z, a4a.w, a4b.x, a4b.y, a4b.z, a4b.w};
            float br[4] = {b4.x, b4.y, b4.z, b4.w};
            #pragma unroll
            for (int i = 0; i < 8; i++)
                #pragma unroll
                for (int j = 0; j < 4; j++) acc[i][j] += ar[i] * br[j];
        }
        __syncthreads();
    }

    int m0 = bm + ty * 8;
    int win = m0 / NTOK, token = m0 - win * NTOK;
    #pragma unroll
    for (int i = 0; i < 8; i++) {
        int b = win >> 6, widx = win & 63;
        int wh = widx >> 3, ww = widx & 7;
        int th = token / 7, tw = token - th * 7;
        int h = wh * 7 + th + SHIFTV; if (h >= HH)  h -= HH;
        int w = ww * 7 + tw + SHIFTV; if (w >= WWI) w -= WWI;
        int ob = ((b * HH + h) * WWI + w) * CC;
        #pragma unroll
        for (int j = 0; j < 4; j++) {
            int n = bn + tx * 4 + j;
            out[ob + n] = x[ob + n] + acc[i][j] + proj_b[n];
        }
        token++; if (token == NTOK) { token = 0; win++; }
    }
}

extern "C" void kernel_launch(void* const* d_in, const int* in_sizes, int n_in,
                              void* d_out, int out_size)
{
    const float* x          = (const float*)d_in[0];
    const float* qkv_w      = (const float*)d_in[1];
    const float* qkv_b      = (const float*)d_in[2];
    const float* proj_w     = (const float*)d_in[3];
    const float* proj_b     = (const float*)d_in[4];
    const float* bias_table = (const float*)d_in[5];
    float* out = (float*)d_out;

    dim3 g1(MTOT / BM1, NQKV / BN1);   // 392 x 24
    qkv_kernel<<<g1, 256>>>(x, qkv_w, qkv_b);

    attn_kernel<<<NWIN * NHEADS, 256>>>(bias_table);

    dim3 g3(MTOT / BM1, CC / BN1);     // 392 x 8
    proj_kernel<<<g3, 256>>>(x, proj_w, proj_b, out);
}

// round 5
// speedup vs baseline: 2.2153x; 2.2153x over previous
#include <cuda_runtime.h>
#include <cuda_bf16.h>

#define BB 16
#define HH 56
#define WWI 56
#define CC 512
#define NHEADS 16
#define DH 32
#define NTOK 49
#define SHIFTV 3
#define NWIN 1024            // B * 64 windows
#define MTOT (NWIN * NTOK)   // 50176
#define NQKV 1536
#define QKV_STRIDE (NWIN * NHEADS * NTOK * DH)

// Scratch (device globals; no allocations allowed)
__device__ float g_qkv[3 * QKV_STRIDE];   // [which][win][head][tok][d]
__device__ float g_ao[MTOT * CC];

// m16n8k8 tf32 mma (row.col), fp32 accumulate
__device__ __forceinline__ void mma_tf32(float* d, const float* a, const float* b) {
    asm volatile(
        "mma.sync.aligned.m16n8k8.row.col.f32.tf32.tf32.f32 "
        "{%0,%1,%2,%3}, {%4,%5,%6,%7}, {%8,%9}, {%0,%1,%2,%3};\n"
        : "+f"(d[0]), "+f"(d[1]), "+f"(d[2]), "+f"(d[3])
        : "r"(__float_as_uint(a[0])), "r"(__float_as_uint(a[1])),
          "r"(__float_as_uint(a[2])), "r"(__float_as_uint(a[3])),
          "r"(__float_as_uint(b[0])), "r"(__float_as_uint(b[1])));
}

// ---------------------------------------------------------------------------
// GEMM tiling: 128 x 128 x 16, 256 threads, warps 4x2, each warp 32x64
// ---------------------------------------------------------------------------
#define BM 128
#define BN 128
#define BK 16

// QKV GEMM (tf32 tensor): A = shifted/window-gathered x, B = qkv_w [512,1536]
__global__ __launch_bounds__(256, 2) void qkv_kernel(
    const float* __restrict__ x,
    const float* __restrict__ qkv_w,
    const float* __restrict__ qkv_b)
{
    __shared__ float As[BM][20];     // stride 20: conflict-free frag loads
    __shared__ float Bs[BK][136];    // stride 136: conflict-free frag loads
    __shared__ int rowBase[BM];

    const int tid = threadIdx.x;
    const int lane = tid & 31, wid = tid >> 5;
    const int warp_m = wid & 3, warp_n = wid >> 2;
    const int bm = blockIdx.x * BM, bn = blockIdx.y * BN;

    if (tid < BM) {
        int m = bm + tid;
        int win = m / NTOK, token = m - win * NTOK;
        int b = win >> 6, widx = win & 63;
        int wh = widx >> 3, ww = widx & 7;
        int th = token / 7, tw = token - th * 7;
        int h = wh * 7 + th + SHIFTV; if (h >= HH)  h -= HH;
        int w = ww * 7 + tw + SHIFTV; if (w >= WWI) w -= WWI;
        rowBase[tid] = ((b * HH + h) * WWI + w) * CC;
    }
    __syncthreads();

    const int r0 = tid >> 2, seg = (tid & 3) * 4;
    const int rbA0 = rowBase[r0], rbA1 = rowBase[r0 + 64];
    const int kb = tid >> 4, nb = (tid & 15) * 4;

    float4 ra0 = *(const float4*)(x + rbA0 + seg);
    float4 ra1 = *(const float4*)(x + rbA1 + seg);
    float4 rb0 = *(const float4*)(qkv_w + kb * NQKV + bn + nb);
    float4 rb1 = *(const float4*)(qkv_w + kb * NQKV + bn + nb + 64);

    float acc[2][8][4];
    #pragma unroll
    for (int mi = 0; mi < 2; mi++)
        #pragma unroll
        for (int ni = 0; ni < 8; ni++)
            #pragma unroll
            for (int c = 0; c < 4; c++) acc[mi][ni][c] = 0.f;

    for (int k0 = 0; k0 < CC; k0 += BK) {
        *(float4*)&As[r0][seg] = ra0;
        *(float4*)&As[r0 + 64][seg] = ra1;
        *(float4*)&Bs[kb][nb] = rb0;
        *(float4*)&Bs[kb][nb + 64] = rb1;
        __syncthreads();
        if (k0 + BK < CC) {
            ra0 = *(const float4*)(x + rbA0 + k0 + BK + seg);
            ra1 = *(const float4*)(x + rbA1 + k0 + BK + seg);
            rb0 = *(const float4*)(qkv_w + (k0 + BK + kb) * NQKV + bn + nb);
            rb1 = *(const float4*)(qkv_w + (k0 + BK + kb) * NQKV + bn + nb + 64);
        }
        #pragma unroll
        for (int ks = 0; ks < 2; ks++) {
            float af[2][4], bf[8][2];
            const int kc = ks * 8 + (lane & 3);
            #pragma unroll
            for (int mi = 0; mi < 2; mi++) {
                int ar = warp_m * 32 + mi * 16 + (lane >> 2);
                af[mi][0] = As[ar][kc];     af[mi][1] = As[ar + 8][kc];
                af[mi][2] = As[ar][kc + 4]; af[mi][3] = As[ar + 8][kc + 4];
            }
            #pragma unroll
            for (int ni = 0; ni < 8; ni++) {
                int bc = warp_n * 64 + ni * 8 + (lane >> 2);
                bf[ni][0] = Bs[kc][bc];
                bf[ni][1] = Bs[kc + 4][bc];
            }
            #pragma unroll
            for (int mi = 0; mi < 2; mi++)
                #pragma unroll
                for (int ni = 0; ni < 8; ni++)
                    mma_tf32(acc[mi][ni], af[mi], bf[ni]);
        }
        __syncthreads();
    }

    const float scale = 0.17677669529663687f;   // 32^-0.5
    #pragma unroll
    for (int mi = 0; mi < 2; mi++) {
        #pragma unroll
        for (int half = 0; half < 2; half++) {
            int m = bm + warp_m * 32 + mi * 16 + (lane >> 2) + half * 8;
            int win = m / NTOK, token = m - win * NTOK;
            #pragma unroll
            for (int ni = 0; ni < 8; ni++) {
                #pragma unroll
                for (int cj = 0; cj < 2; cj++) {
                    int n = bn + warp_n * 64 + ni * 8 + 2 * (lane & 3) + cj;
                    float val = acc[mi][ni][half * 2 + cj] + qkv_b[n];
                    int which = n >> 9;
                    int head = (n >> 5) & 15;
                    int dim = n & 31;
                    if (which == 0) val *= scale;
                    g_qkv[which * QKV_STRIDE +
                          ((win * NHEADS + head) * NTOK + token) * DH + dim] = val;
                }
            }
        }
    }
}

// ---------------------------------------------------------------------------
// Fused attention: one block per (window, head). fp32 SIMT.
// ---------------------------------------------------------------------------
__global__ __launch_bounds__(256) void attn_kernel(const float* __restrict__ bias_table)
{
    __shared__ float q_s[NTOK * DH];
    __shared__ float kT[DH * NTOK];
    __shared__ float v_s[NTOK * DH];
    __shared__ float S[NTOK * NTOK];
    __shared__ float biasH[169];
    __shared__ int reg_s[NTOK];

    const int tid = threadIdx.x;
    const int whid = blockIdx.x;
    const int win = whid >> 4;
    const int head = whid & 15;
    const int base = whid * (NTOK * DH);

    for (int idx = tid; idx < NTOK * DH; idx += 256) {
        q_s[idx] = g_qkv[base + idx];
        v_s[idx] = g_qkv[2 * QKV_STRIDE + base + idx];
        float kv = g_qkv[QKV_STRIDE + base + idx];
        int tok = idx >> 5, dim = idx & 31;
        kT[dim * NTOK + tok] = kv;
    }
    if (tid < 169) biasH[tid] = bias_table[tid * NHEADS + head];

    const int widx = win & 63;
    const int wh = widx >> 3, ww = widx & 7;
    const bool masked = (wh == 7) || (ww == 7);
    if (tid < NTOK) {
        int th = tid / 7, tw = tid - th * 7;
        int hs = wh * 7 + th, wsc = ww * 7 + tw;
        int rh = hs < 49 ? 0 : (hs < 53 ? 1 : 2);
        int rw = wsc < 49 ? 0 : (wsc < 53 ? 1 : 2);
        reg_s[tid] = rh * 3 + rw;
    }
    __syncthreads();

    for (int p = tid; p < NTOK * NTOK; p += 256) {
        int i = p / NTOK, j = p - i * NTOK;
        float s = 0.f;
        #pragma unroll
        for (int t = 0; t < DH; t++) s += q_s[i * DH + t] * kT[t * NTOK + j];
        int ri = i / 7, ci = i - ri * 7;
        int rj = j / 7, cj = j - rj * 7;
        s += biasH[(ri - rj + 6) * 13 + (ci - cj + 6)];
        if (masked && reg_s[i] != reg_s[j]) s -= 100.f;
        S[p] = s;
    }
    __syncthreads();

    const int lane = tid & 31, warp = tid >> 5;
    for (int i = warp; i < NTOK; i += 8) {
        float v1 = (lane < NTOK) ? S[i * NTOK + lane] : -1e30f;
        float v2 = (lane + 32 < NTOK) ? S[i * NTOK + lane + 32] : -1e30f;
        float m = fmaxf(v1, v2);
        #pragma unroll
        for (int o = 16; o > 0; o >>= 1) m = fmaxf(m, __shfl_xor_sync(0xffffffffu, m, o));
        float e1 = (lane < NTOK) ? __expf(v1 - m) : 0.f;
        float e2 = (lane + 32 < NTOK) ? __expf(v2 - m) : 0.f;
        float sum = e1 + e2;
        #pragma unroll
        for (int o = 16; o > 0; o >>= 1) sum += __shfl_xor_sync(0xffffffffu, sum, o);
        float inv = 1.f / sum;
        if (lane < NTOK) S[i * NTOK + lane] = e1 * inv;
        if (lane + 32 < NTOK) S[i * NTOK + lane + 32] = e2 * inv;
    }
    __syncthreads();

    const int outbase = (win * NTOK) * CC + head * DH;
    for (int p = tid; p < NTOK * DH; p += 256) {
        int i = p >> 5, dim = p & 31;
        float o = 0.f;
        #pragma unroll
        for (int j = 0; j < NTOK; j++) o += S[i * NTOK + j] * v_s[j * DH + dim];
        g_ao[outbase + i * CC + dim] = o;
    }
}

// ---------------------------------------------------------------------------
// Proj GEMM (tf32 tensor) + bias + window-reverse + inv shift + residual
// ---------------------------------------------------------------------------
__global__ __launch_bounds__(256, 2) void proj_kernel(
    const float* __restrict__ x,
    const float* __restrict__ proj_w,
    const float* __restrict__ proj_b,
    float* __restrict__ out)
{
    __shared__ float As[BM][20];
    __shared__ float Bs[BK][136];

    const int tid = threadIdx.x;
    const int lane = tid & 31, wid = tid >> 5;
    const int warp_m = wid & 3, warp_n = wid >> 2;
    const int bm = blockIdx.x * BM, bn = blockIdx.y * BN;

    const int r0 = tid >> 2, seg = (tid & 3) * 4;
    const int kb = tid >> 4, nb = (tid & 15) * 4;
    const float* A = g_ao;

    float4 ra0 = *(const float4*)(A + (bm + r0) * CC + seg);
    float4 ra1 = *(const float4*)(A + (bm + r0 + 64) * CC + seg);
    float4 rb0 = *(const float4*)(proj_w + kb * CC + bn + nb);
    float4 rb1 = *(const float4*)(proj_w + kb * CC + bn + nb + 64);

    float acc[2][8][4];
    #pragma unroll
    for (int mi = 0; mi < 2; mi++)
        #pragma unroll
        for (int ni = 0; ni < 8; ni++)
            #pragma unroll
            for (int c = 0; c < 4; c++) acc[mi][ni][c] = 0.f;

    for (int k0 = 0; k0 < CC; k0 += BK) {
        *(float4*)&As[r0][seg] = ra0;
        *(float4*)&As[r0 + 64][seg] = ra1;
        *(float4*)&Bs[kb][nb] = rb0;
        *(float4*)&Bs[kb][nb + 64] = rb1;
        __syncthreads();
        if (k0 + BK < CC) {
            ra0 = *(const float4*)(A + (bm + r0) * CC + k0 + BK + seg);
            ra1 = *(const float4*)(A + (bm + r0 + 64) * CC + k0 + BK + seg);
            rb0 = *(const float4*)(proj_w + (k0 + BK + kb) * CC + bn + nb);
            rb1 = *(const float4*)(proj_w + (k0 + BK + kb) * CC + bn + nb + 64);
        }
        #pragma unroll
        for (int ks = 0; ks < 2; ks++) {
            float af[2][4], bf[8][2];
            const int kc = ks * 8 + (lane & 3);
            #pragma unroll
            for (int mi = 0; mi < 2; mi++) {
                int ar = warp_m * 32 + mi * 16 + (lane >> 2);
                af[mi][0] = As[ar][kc];     af[mi][1] = As[ar + 8][kc];
                af[mi][2] = As[ar][kc + 4]; af[mi][3] = As[ar + 8][kc + 4];
            }
            #pragma unroll
            for (int ni = 0; ni < 8; ni++) {
                int bc = warp_n * 64 + ni * 8 + (lane >> 2);
                bf[ni][0] = Bs[kc][bc];
                bf[ni][1] = Bs[kc + 4][bc];
            }
            #pragma unroll
            for (int mi = 0; mi < 2; mi++)
                #pragma unroll
                for (int ni = 0; ni < 8; ni++)
                    mma_tf32(acc[mi][ni], af[mi], bf[ni]);
        }
        __syncthreads();
    }

    #pragma unroll
    for (int mi = 0; mi < 2; mi++) {
        #pragma unroll
        for (int half = 0; half < 2; half++) {
            int m = bm + warp_m * 32 + mi * 16 + (lane >> 2) + half * 8;
            int win = m / NTOK, token = m - win * NTOK;
            int b = win >> 6, widx = win & 63;
            int wh = widx >> 3, ww = widx & 7;
            int th = token / 7, tw = token - th * 7;
            int h = wh * 7 + th + SHIFTV; if (h >= HH)  h -= HH;
            int w = ww * 7 + tw + SHIFTV; if (w >= WWI) w -= WWI;
            int ob = ((b * HH + h) * WWI + w) * CC;
            #pragma unroll
            for (int ni = 0; ni < 8; ni++) {
                #pragma unroll
                for (int cj = 0; cj < 2; cj++) {
                    int n = bn + warp_n * 64 + ni * 8 + 2 * (lane & 3) + cj;
                    out[ob + n] = x[ob + n] + acc[mi][ni][half * 2 + cj] + proj_b[n];
                }
            }
        }
    }
}

extern "C" void kernel_launch(void* const* d_in, const int* in_sizes, int n_in,
                              void* d_out, int out_size)
{
    const float* x          = (const float*)d_in[0];
    const float* qkv_w      = (const float*)d_in[1];
    const float* qkv_b      = (const float*)d_in[2];
    const float* proj_w     = (const float*)d_in[3];
    const float* proj_b     = (const float*)d_in[4];
    const float* bias_table = (const float*)d_in[5];
    float* out = (float*)d_out;

    dim3 g1(MTOT / BM, NQKV / BN);   // 392 x 12
    qkv_kernel<<<g1, 256>>>(x, qkv_w, qkv_b);

    attn_kernel<<<NWIN * NHEADS, 256>>>(bias_table);

    dim3 g3(MTOT / BM, CC / BN);     // 392 x 4
    proj_kernel<<<g3, 256>>>(x, proj_w, proj_b, out);
}

// round 8
// speedup vs baseline: 2.7679x; 1.2495x over previous
#include <cuda_runtime.h>
#include <cuda_bf16.h>

#define BB 16
#define HH 56
#define WWI 56
#define CC 512
#define NHEADS 16
#define DH 32
#define NTOK 49
#define SHIFTV 3
#define NWIN 1024            // B * 64 windows
#define MTOT (NWIN * NTOK)   // 50176
#define NQKV 1536
#define QKV_STRIDE (NWIN * NHEADS * NTOK * DH)

// Scratch (device globals; no allocations allowed)
__device__ float g_qkv[3 * QKV_STRIDE];   // [which][win][head][tok][d]
__device__ float g_ao[MTOT * CC];

// m16n8k8 tf32 mma (row.col), fp32 accumulate
__device__ __forceinline__ void mma_tf32(float* d, const float* a, const float* b) {
    asm volatile(
        "mma.sync.aligned.m16n8k8.row.col.f32.tf32.tf32.f32 "
        "{%0,%1,%2,%3}, {%4,%5,%6,%7}, {%8,%9}, {%0,%1,%2,%3};\n"
        : "+f"(d[0]), "+f"(d[1]), "+f"(d[2]), "+f"(d[3])
        : "r"(__float_as_uint(a[0])), "r"(__float_as_uint(a[1])),
          "r"(__float_as_uint(a[2])), "r"(__float_as_uint(a[3])),
          "r"(__float_as_uint(b[0])), "r"(__float_as_uint(b[1])));
}

// ---------------------------------------------------------------------------
// GEMM tiling: 128 x 128 x 16, 256 threads, warps 4x2, each warp 32x64
// ---------------------------------------------------------------------------
#define BM 128
#define BN 128
#define BK 16

// QKV GEMM (tf32 tensor): A = shifted/window-gathered x, B = qkv_w [512,1536]
__global__ __launch_bounds__(256, 2) void qkv_kernel(
    const float* __restrict__ x,
    const float* __restrict__ qkv_w,
    const float* __restrict__ qkv_b)
{
    __shared__ float As[BM][20];     // stride 20: conflict-free frag loads
    __shared__ float Bs[BK][136];    // stride 136: conflict-free frag loads
    __shared__ int rowBase[BM];

    const int tid = threadIdx.x;
    const int lane = tid & 31, wid = tid >> 5;
    const int warp_m = wid & 3, warp_n = wid >> 2;
    const int bm = blockIdx.x * BM, bn = blockIdx.y * BN;

    if (tid < BM) {
        int m = bm + tid;
        int win = m / NTOK, token = m - win * NTOK;
        int b = win >> 6, widx = win & 63;
        int wh = widx >> 3, ww = widx & 7;
        int th = token / 7, tw = token - th * 7;
        int h = wh * 7 + th + SHIFTV; if (h >= HH)  h -= HH;
        int w = ww * 7 + tw + SHIFTV; if (w >= WWI) w -= WWI;
        rowBase[tid] = ((b * HH + h) * WWI + w) * CC;
    }
    __syncthreads();

    const int r0 = tid >> 2, seg = (tid & 3) * 4;
    const int rbA0 = rowBase[r0], rbA1 = rowBase[r0 + 64];
    const int kb = tid >> 4, nb = (tid & 15) * 4;

    float4 ra0 = *(const float4*)(x + rbA0 + seg);
    float4 ra1 = *(const float4*)(x + rbA1 + seg);
    float4 rb0 = *(const float4*)(qkv_w + kb * NQKV + bn + nb);
    float4 rb1 = *(const float4*)(qkv_w + kb * NQKV + bn + nb + 64);

    float acc[2][8][4];
    #pragma unroll
    for (int mi = 0; mi < 2; mi++)
        #pragma unroll
        for (int ni = 0; ni < 8; ni++)
            #pragma unroll
            for (int c = 0; c < 4; c++) acc[mi][ni][c] = 0.f;

    for (int k0 = 0; k0 < CC; k0 += BK) {
        *(float4*)&As[r0][seg] = ra0;
        *(float4*)&As[r0 + 64][seg] = ra1;
        *(float4*)&Bs[kb][nb] = rb0;
        *(float4*)&Bs[kb][nb + 64] = rb1;
        __syncthreads();
        if (k0 + BK < CC) {
            ra0 = *(const float4*)(x + rbA0 + k0 + BK + seg);
            ra1 = *(const float4*)(x + rbA1 + k0 + BK + seg);
            rb0 = *(const float4*)(qkv_w + (k0 + BK + kb) * NQKV + bn + nb);
            rb1 = *(const float4*)(qkv_w + (k0 + BK + kb) * NQKV + bn + nb + 64);
        }
        #pragma unroll
        for (int ks = 0; ks < 2; ks++) {
            float af[2][4], bf[8][2];
            const int kc = ks * 8 + (lane & 3);
            #pragma unroll
            for (int mi = 0; mi < 2; mi++) {
                int ar = warp_m * 32 + mi * 16 + (lane >> 2);
                af[mi][0] = As[ar][kc];     af[mi][1] = As[ar + 8][kc];
                af[mi][2] = As[ar][kc + 4]; af[mi][3] = As[ar + 8][kc + 4];
            }
            #pragma unroll
            for (int ni = 0; ni < 8; ni++) {
                int bc = warp_n * 64 + ni * 8 + (lane >> 2);
                bf[ni][0] = Bs[kc][bc];
                bf[ni][1] = Bs[kc + 4][bc];
            }
            #pragma unroll
            for (int mi = 0; mi < 2; mi++)
                #pragma unroll
                for (int ni = 0; ni < 8; ni++)
                    mma_tf32(acc[mi][ni], af[mi], bf[ni]);
        }
        __syncthreads();
    }

    const float scale = 0.17677669529663687f;   // 32^-0.5
    #pragma unroll
    for (int mi = 0; mi < 2; mi++) {
        #pragma unroll
        for (int half = 0; half < 2; half++) {
            int m = bm + warp_m * 32 + mi * 16 + (lane >> 2) + half * 8;
            int win = m / NTOK, token = m - win * NTOK;
            #pragma unroll
            for (int ni = 0; ni < 8; ni++) {
                #pragma unroll
                for (int cj = 0; cj < 2; cj++) {
                    int n = bn + warp_n * 64 + ni * 8 + 2 * (lane & 3) + cj;
                    float val = acc[mi][ni][half * 2 + cj] + qkv_b[n];
                    int which = n >> 9;
                    int head = (n >> 5) & 15;
                    int dim = n & 31;
                    if (which == 0) val *= scale;
                    g_qkv[which * QKV_STRIDE +
                          ((win * NHEADS + head) * NTOK + token) * DH + dim] = val;
                }
            }
        }
    }
}

// ---------------------------------------------------------------------------
// Fused attention v2: tf32 tensor-core S=QK^T and O=PV, padded 49 -> 64.
// One block per (window, head), 256 threads = 8 warps (4x2 warp grid).
// Padded S cols pre-stored as -1e30 -> softmax zeros them -> PV k-padding
// self-masks. v_s padding rows zeroed so 0 * garbage never makes NaN.
// ---------------------------------------------------------------------------
#define NP 64   // padded token count

__global__ __launch_bounds__(256) void attn_kernel(const float* __restrict__ bias_table)
{
    __shared__ float q_s[NP][36];    // [tok][dim]   stride 36 (≡4 mod 32): A-frags CF
    __shared__ float kT[DH][72];     // [dim][tok]   stride 72 (≡8 mod 32): B-frags CF
    __shared__ float v_s[NP][40];    // [tok][dim]   stride 40 (≡8 mod 32): B-frags CF
    __shared__ float S[NP][68];      // [row][col]   stride 68 (≡4 mod 32): A-frags CF
    __shared__ float biasH[169];
    __shared__ int reg_s[NTOK];

    const int tid = threadIdx.x;
    const int lane = tid & 31, wid = tid >> 5;
    const int warp_m = wid & 3, warp_n = wid >> 2;   // 4 x 2
    const int whid = blockIdx.x;
    const int win = whid >> 4;
    const int head = whid & 15;
    const int base = whid * (NTOK * DH);

    // load q/k/v (1568 floats each), coalesced reads
    for (int idx = tid; idx < NTOK * DH; idx += 256) {
        int tok = idx >> 5, dim = idx & 31;
        q_s[tok][dim] = g_qkv[base + idx];
        kT[dim][tok]  = g_qkv[QKV_STRIDE + base + idx];
        v_s[tok][dim] = g_qkv[2 * QKV_STRIDE + base + idx];
    }
    // zero v_s padding rows (tok 49..63) so P(=0) * v_pad stays 0
    for (int idx = tid; idx < (NP - NTOK) * DH; idx += 256)
        v_s[NTOK + (idx >> 5)][idx & 31] = 0.f;
    if (tid < 169) biasH[tid] = bias_table[tid * NHEADS + head];

    const int widx = win & 63;
    const int wwh = widx >> 3, www = widx & 7;
    const bool masked = (wwh == 7) || (www == 7);
    if (tid < NTOK) {
        int th = tid / 7, tw = tid - th * 7;
        int hs = wwh * 7 + th, wsc = www * 7 + tw;
        int rh = hs < 49 ? 0 : (hs < 53 ? 1 : 2);
        int rw = wsc < 49 ? 0 : (wsc < 53 ? 1 : 2);
        reg_s[tid] = rh * 3 + rw;
    }
    __syncthreads();

    // ---- S = q * k^T : warp computes rows [warp_m*16, +16), cols [warp_n*32, +32)
    float accS[4][4];
    #pragma unroll
    for (int ni = 0; ni < 4; ni++)
        #pragma unroll
        for (int c = 0; c < 4; c++) accS[ni][c] = 0.f;

    const int ar = warp_m * 16 + (lane >> 2);
    #pragma unroll
    for (int ks = 0; ks < 4; ks++) {
        const int kc = ks * 8 + (lane & 3);
        float af[4];
        af[0] = q_s[ar][kc];     af[1] = q_s[ar + 8][kc];
        af[2] = q_s[ar][kc + 4]; af[3] = q_s[ar + 8][kc + 4];
        #pragma unroll
        for (int ni = 0; ni < 4; ni++) {
            int bc = warp_n * 32 + ni * 8 + (lane >> 2);
            float bf[2];
            bf[0] = kT[kc][bc];
            bf[1] = kT[kc + 4][bc];
            mma_tf32(accS[ni], af, bf);
        }
    }

    // store S with bias + shift mask; padded cols get -1e30
    #pragma unroll
    for (int half = 0; half < 2; half++) {
        int i = ar + half * 8;
        int ri = i / 7, ci = i - ri * 7;      // valid when i < 49
        #pragma unroll
        for (int ni = 0; ni < 4; ni++) {
            #pragma unroll
            for (int cj = 0; cj < 2; cj++) {
                int j = warp_n * 32 + ni * 8 + 2 * (lane & 3) + cj;
                float val = accS[ni][half * 2 + cj];
                if (j >= NTOK) {
                    val = -1e30f;
                } else if (i < NTOK) {
                    int rj = j / 7, cjj = j - rj * 7;
                    val += biasH[(ri - rj + 6) * 13 + (ci - cjj + 6)];
                    if (masked && reg_s[i] != reg_s[j]) val -= 100.f;
                }
                S[i][j] = val;
            }
        }
    }
    __syncthreads();

    // ---- softmax over valid rows (padded cols are -1e30 -> exp -> 0)
    for (int i = wid; i < NTOK; i += 8) {
        float v1 = S[i][lane];
        float v2 = S[i][lane + 32];
        float m = fmaxf(v1, v2);
        #pragma unroll
        for (int o = 16; o > 0; o >>= 1) m = fmaxf(m, __shfl_xor_sync(0xffffffffu, m, o));
        float e1 = __expf(v1 - m);
        float e2 = __expf(v2 - m);
        float sum = e1 + e2;
        #pragma unroll
        for (int o = 16; o > 0; o >>= 1) sum += __shfl_xor_sync(0xffffffffu, sum, o);
        float inv = 1.f / sum;
        S[i][lane] = e1 * inv;
        S[i][lane + 32] = e2 * inv;
    }
    __syncthreads();

    // ---- O = P * V : warp computes rows [warp_m*16, +16), dims [warp_n*16, +16)
    float accO[2][4];
    #pragma unroll
    for (int ni = 0; ni < 2; ni++)
        #pragma unroll
        for (int c = 0; c < 4; c++) accO[ni][c] = 0.f;

    #pragma unroll
    for (int ks = 0; ks < 8; ks++) {
        const int kc = ks * 8 + (lane & 3);
        float af[4];
        af[0] = S[ar][kc];     af[1] = S[ar + 8][kc];
        af[2] = S[ar][kc + 4]; af[3] = S[ar + 8][kc + 4];
        #pragma unroll
        for (int ni = 0; ni < 2; ni++) {
            int bc = warp_n * 16 + ni * 8 + (lane >> 2);
            float bf[2];
            bf[0] = v_s[kc][bc];
            bf[1] = v_s[kc + 4][bc];
            mma_tf32(accO[ni], af, bf);
        }
    }

    const int outbase = (win * NTOK) * CC + head * DH;
    #pragma unroll
    for (int half = 0; half < 2; half++) {
        int i = ar + half * 8;
        if (i < NTOK) {
            #pragma unroll
            for (int ni = 0; ni < 2; ni++) {
                #pragma unroll
                for (int cj = 0; cj < 2; cj++) {
                    int d = warp_n * 16 + ni * 8 + 2 * (lane & 3) + cj;
                    g_ao[outbase + i * CC + d] = accO[ni][half * 2 + cj];
                }
            }
        }
    }
}

// ---------------------------------------------------------------------------
// Proj GEMM (tf32 tensor) + bias + window-reverse + inv shift + residual
// ---------------------------------------------------------------------------
__global__ __launch_bounds__(256, 2) void proj_kernel(
    const float* __restrict__ x,
    const float* __restrict__ proj_w,
    const float* __restrict__ proj_b,
    float* __restrict__ out)
{
    __shared__ float As[BM][20];
    __shared__ float Bs[BK][136];

    const int tid = threadIdx.x;
    const int lane = tid & 31, wid = tid >> 5;
    const int warp_m = wid & 3, warp_n = wid >> 2;
    const int bm = blockIdx.x * BM, bn = blockIdx.y * BN;

    const int r0 = tid >> 2, seg = (tid & 3) * 4;
    const int kb = tid >> 4, nb = (tid & 15) * 4;
    const float* A = g_ao;

    float4 ra0 = *(const float4*)(A + (bm + r0) * CC + seg);
    float4 ra1 = *(const float4*)(A + (bm + r0 + 64) * CC + seg);
    float4 rb0 = *(const float4*)(proj_w + kb * CC + bn + nb);
    float4 rb1 = *(const float4*)(proj_w + kb * CC + bn + nb + 64);

    float acc[2][8][4];
    #pragma unroll
    for (int mi = 0; mi < 2; mi++)
        #pragma unroll
        for (int ni = 0; ni < 8; ni++)
            #pragma unroll
            for (int c = 0; c < 4; c++) acc[mi][ni][c] = 0.f;

    for (int k0 = 0; k0 < CC; k0 += BK) {
        *(float4*)&As[r0][seg] = ra0;
        *(float4*)&As[r0 + 64][seg] = ra1;
        *(float4*)&Bs[kb][nb] = rb0;
        *(float4*)&Bs[kb][nb + 64] = rb1;
        __syncthreads();
        if (k0 + BK < CC) {
            ra0 = *(const float4*)(A + (bm + r0) * CC + k0 + BK + seg);
            ra1 = *(const float4*)(A + (bm + r0 + 64) * CC + k0 + BK + seg);
            rb0 = *(const float4*)(proj_w + (k0 + BK + kb) * CC + bn + nb);
            rb1 = *(const float4*)(proj_w + (k0 + BK + kb) * CC + bn + nb + 64);
        }
        #pragma unroll
        for (int ks = 0; ks < 2; ks++) {
            float af[2][4], bf[8][2];
            const int kc = ks * 8 + (lane & 3);
            #pragma unroll
            for (int mi = 0; mi < 2; mi++) {
                int ar = warp_m * 32 + mi * 16 + (lane >> 2);
                af[mi][0] = As[ar][kc];     af[mi][1] = As[ar + 8][kc];
                af[mi][2] = As[ar][kc + 4]; af[mi][3] = As[ar + 8][kc + 4];
            }
            #pragma unroll
            for (int ni = 0; ni < 8; ni++) {
                int bc = warp_n * 64 + ni * 8 + (lane >> 2);
                bf[ni][0] = Bs[kc][bc];
                bf[ni][1] = Bs[kc + 4][bc];
            }
            #pragma unroll
            for (int mi = 0; mi < 2; mi++)
                #pragma unroll
                for (int ni = 0; ni < 8; ni++)
                    mma_tf32(acc[mi][ni], af[mi], bf[ni]);
        }
        __syncthreads();
    }

    #pragma unroll
    for (int mi = 0; mi < 2; mi++) {
        #pragma unroll
        for (int half = 0; half < 2; half++) {
            int m = bm + warp_m * 32 + mi * 16 + (lane >> 2) + half * 8;
            int win = m / NTOK, token = m - win * NTOK;
            int b = win >> 6, widx = win & 63;
            int wh = widx >> 3, ww = widx & 7;
            int th = token / 7, tw = token - th * 7;
            int h = wh * 7 + th + SHIFTV; if (h >= HH)  h -= HH;
            int w = ww * 7 + tw + SHIFTV; if (w >= WWI) w -= WWI;
            int ob = ((b * HH + h) * WWI + w) * CC;
            #pragma unroll
            for (int ni = 0; ni < 8; ni++) {
                #pragma unroll
                for (int cj = 0; cj < 2; cj++) {
                    int n = bn + warp_n * 64 + ni * 8 + 2 * (lane & 3) + cj;
                    out[ob + n] = x[ob + n] + acc[mi][ni][half * 2 + cj] + proj_b[n];
                }
            }
        }
    }
}

extern "C" void kernel_launch(void* const* d_in, const int* in_sizes, int n_in,
                              void* d_out, int out_size)
{
    const float* x          = (const float*)d_in[0];
    const float* qkv_w      = (const float*)d_in[1];
    const float* qkv_b      = (const float*)d_in[2];
    const float* proj_w     = (const float*)d_in[3];
    const float* proj_b     = (const float*)d_in[4];
    const float* bias_table = (const float*)d_in[5];
    float* out = (float*)d_out;

    dim3 g1(MTOT / BM, NQKV / BN);   // 392 x 12
    qkv_kernel<<<g1, 256>>>(x, qkv_w, qkv_b);

    attn_kernel<<<NWIN * NHEADS, 256>>>(bias_table);

    dim3 g3(MTOT / BM, CC / BN);     // 392 x 4
    proj_kernel<<<g3, 256>>>(x, proj_w, proj_b, out);
}

// round 9
// speedup vs baseline: 3.3777x; 1.2203x over previous
#include <cuda_runtime.h>
#include <cuda_bf16.h>

#define BB 16
#define HH 56
#define WWI 56
#define CC 512
#define NHEADS 16
#define DH 32
#define NTOK 49
#define SHIFTV 3
#define NWIN 1024            // B * 64 windows
#define MTOT (NWIN * NTOK)   // 50176
#define NQKV 1536
#define QKV_STRIDE (NWIN * NHEADS * NTOK * DH)

// Scratch (device globals; no allocations allowed)
__device__ float g_qkv[3 * QKV_STRIDE];   // [which][win][head][tok][d]
__device__ float g_ao[MTOT * CC];

// m16n8k8 tf32 mma (row.col), fp32 accumulate — used by attention
__device__ __forceinline__ void mma_tf32(float* d, const float* a, const float* b) {
    asm volatile(
        "mma.sync.aligned.m16n8k8.row.col.f32.tf32.tf32.f32 "
        "{%0,%1,%2,%3}, {%4,%5,%6,%7}, {%8,%9}, {%0,%1,%2,%3};\n"
        : "+f"(d[0]), "+f"(d[1]), "+f"(d[2]), "+f"(d[3])
        : "r"(__float_as_uint(a[0])), "r"(__float_as_uint(a[1])),
          "r"(__float_as_uint(a[2])), "r"(__float_as_uint(a[3])),
          "r"(__float_as_uint(b[0])), "r"(__float_as_uint(b[1])));
}

// m16n8k16 bf16 mma (row.col), fp32 accumulate — used by the two big GEMMs
__device__ __forceinline__ void mma_bf16(float* d, const unsigned* a, const unsigned* b) {
    asm volatile(
        "mma.sync.aligned.m16n8k16.row.col.f32.bf16.bf16.f32 "
        "{%0,%1,%2,%3}, {%4,%5,%6,%7}, {%8,%9}, {%0,%1,%2,%3};\n"
        : "+f"(d[0]), "+f"(d[1]), "+f"(d[2]), "+f"(d[3])
        : "r"(a[0]), "r"(a[1]), "r"(a[2]), "r"(a[3]),
          "r"(b[0]), "r"(b[1]));
}

__device__ __forceinline__ unsigned pack_bf16(float lo, float hi) {
    __nv_bfloat162 t = __floats2bfloat162_rn(lo, hi);
    return *(unsigned*)&t;
}

// ---------------------------------------------------------------------------
// GEMM tiling: 128 x 128 x 16 (bf16), 256 threads, warps 4x2, warp = 32x64
// As: [m][k-pair] stride 12 words (≡4 mod 32 -> CF frag loads + CF STS.64)
// Bs: [k-pair][n] stride 136 words (8p+n distinct mod 32 -> CF)
// ---------------------------------------------------------------------------
#define BM 128
#define BN 128
#define BK 16

// QKV GEMM (bf16 tensor): A = shifted/window-gathered x, B = qkv_w [512,1536]
__global__ __launch_bounds__(256, 2) void qkv_kernel(
    const float* __restrict__ x,
    const float* __restrict__ qkv_w,
    const float* __restrict__ qkv_b)
{
    __shared__ unsigned As[BM][12];    // 8 bf162 pairs + 4 pad
    __shared__ unsigned Bs[8][136];    // [pair][n], 128 + 8 pad
    __shared__ int rowBase[BM];

    const int tid = threadIdx.x;
    const int lane = tid & 31, wid = tid >> 5;
    const int warp_m = wid & 3, warp_n = wid >> 2;
    const int bm = blockIdx.x * BM, bn = blockIdx.y * BN;

    if (tid < BM) {
        int m = bm + tid;
        int win = m / NTOK, token = m - win * NTOK;
        int b = win >> 6, widx = win & 63;
        int wh = widx >> 3, ww = widx & 7;
        int th = token / 7, tw = token - th * 7;
        int h = wh * 7 + th + SHIFTV; if (h >= HH)  h -= HH;
        int w = ww * 7 + tw + SHIFTV; if (w >= WWI) w -= WWI;
        rowBase[tid] = ((b * HH + h) * WWI + w) * CC;
    }
    __syncthreads();

    // A loader: r0 = tid>>2 (0..63) covers rows r0, r0+64; seg = k offset
    const int r0 = tid >> 2, seg = (tid & 3) * 4;
    const int rbA0 = rowBase[r0], rbA1 = rowBase[r0 + 64];
    // B loader: p = tid>>5 (0..7 k-pairs), nB = (tid&31)*4
    const int pB = tid >> 5, nB = (tid & 31) * 4;

    float4 ra0 = *(const float4*)(x + rbA0 + seg);
    float4 ra1 = *(const float4*)(x + rbA1 + seg);
    float4 rbl = *(const float4*)(qkv_w + (2 * pB) * NQKV + bn + nB);
    float4 rbh = *(const float4*)(qkv_w + (2 * pB + 1) * NQKV + bn + nB);

    float acc[2][8][4];
    #pragma unroll
    for (int mi = 0; mi < 2; mi++)
        #pragma unroll
        for (int ni = 0; ni < 8; ni++)
            #pragma unroll
            for (int c = 0; c < 4; c++) acc[mi][ni][c] = 0.f;

    for (int k0 = 0; k0 < CC; k0 += BK) {
        // pack fp32 -> bf16x2 and store
        As[r0][(seg >> 1)]      = pack_bf16(ra0.x, ra0.y);
        As[r0][(seg >> 1) + 1]  = pack_bf16(ra0.z, ra0.w);
        As[r0 + 64][(seg >> 1)]     = pack_bf16(ra1.x, ra1.y);
        As[r0 + 64][(seg >> 1) + 1] = pack_bf16(ra1.z, ra1.w);
        {
            uint4 bw;
            bw.x = pack_bf16(rbl.x, rbh.x);
            bw.y = pack_bf16(rbl.y, rbh.y);
            bw.z = pack_bf16(rbl.z, rbh.z);
            bw.w = pack_bf16(rbl.w, rbh.w);
            *(uint4*)&Bs[pB][nB] = bw;
        }
        __syncthreads();
        if (k0 + BK < CC) {
            ra0 = *(const float4*)(x + rbA0 + k0 + BK + seg);
            ra1 = *(const float4*)(x + rbA1 + k0 + BK + seg);
            rbl = *(const float4*)(qkv_w + (k0 + BK + 2 * pB) * NQKV + bn + nB);
            rbh = *(const float4*)(qkv_w + (k0 + BK + 2 * pB + 1) * NQKV + bn + nB);
        }
        {
            const int p = lane & 3;
            unsigned af[2][4], bf[8][2];
            #pragma unroll
            for (int mi = 0; mi < 2; mi++) {
                int ar = warp_m * 32 + mi * 16 + (lane >> 2);
                af[mi][0] = As[ar][p];     af[mi][1] = As[ar + 8][p];
                af[mi][2] = As[ar][p + 4]; af[mi][3] = As[ar + 8][p + 4];
            }
            #pragma unroll
            for (int ni = 0; ni < 8; ni++) {
                int bc = warp_n * 64 + ni * 8 + (lane >> 2);
                bf[ni][0] = Bs[p][bc];
                bf[ni][1] = Bs[p + 4][bc];
            }
            #pragma unroll
            for (int mi = 0; mi < 2; mi++)
                #pragma unroll
                for (int ni = 0; ni < 8; ni++)
                    mma_bf16(acc[mi][ni], af[mi], bf[ni]);
        }
        __syncthreads();
    }

    const float scale = 0.17677669529663687f;   // 32^-0.5
    #pragma unroll
    for (int mi = 0; mi < 2; mi++) {
        #pragma unroll
        for (int half = 0; half < 2; half++) {
            int m = bm + warp_m * 32 + mi * 16 + (lane >> 2) + half * 8;
            int win = m / NTOK, token = m - win * NTOK;
            #pragma unroll
            for (int ni = 0; ni < 8; ni++) {
                #pragma unroll
                for (int cj = 0; cj < 2; cj++) {
                    int n = bn + warp_n * 64 + ni * 8 + 2 * (lane & 3) + cj;
                    float val = acc[mi][ni][half * 2 + cj] + qkv_b[n];
                    int which = n >> 9;
                    int head = (n >> 5) & 15;
                    int dim = n & 31;
                    if (which == 0) val *= scale;
                    g_qkv[which * QKV_STRIDE +
                          ((win * NHEADS + head) * NTOK + token) * DH + dim] = val;
                }
            }
        }
    }
}

// ---------------------------------------------------------------------------
// Fused attention v2: tf32 tensor-core S=QK^T and O=PV, padded 49 -> 64.
// ---------------------------------------------------------------------------
#define NP 64   // padded token count

__global__ __launch_bounds__(256) void attn_kernel(const float* __restrict__ bias_table)
{
    __shared__ float q_s[NP][36];
    __shared__ float kT[DH][72];
    __shared__ float v_s[NP][40];
    __shared__ float S[NP][68];
    __shared__ float biasH[169];
    __shared__ int reg_s[NTOK];

    const int tid = threadIdx.x;
    const int lane = tid & 31, wid = tid >> 5;
    const int warp_m = wid & 3, warp_n = wid >> 2;   // 4 x 2
    const int whid = blockIdx.x;
    const int win = whid >> 4;
    const int head = whid & 15;
    const int base = whid * (NTOK * DH);

    for (int idx = tid; idx < NTOK * DH; idx += 256) {
        int tok = idx >> 5, dim = idx & 31;
        q_s[tok][dim] = g_qkv[base + idx];
        kT[dim][tok]  = g_qkv[QKV_STRIDE + base + idx];
        v_s[tok][dim] = g_qkv[2 * QKV_STRIDE + base + idx];
    }
    for (int idx = tid; idx < (NP - NTOK) * DH; idx += 256)
        v_s[NTOK + (idx >> 5)][idx & 31] = 0.f;
    if (tid < 169) biasH[tid] = bias_table[tid * NHEADS + head];

    const int widx = win & 63;
    const int wwh = widx >> 3, www = widx & 7;
    const bool masked = (wwh == 7) || (www == 7);
    if (tid < NTOK) {
        int th = tid / 7, tw = tid - th * 7;
        int hs = wwh * 7 + th, wsc = www * 7 + tw;
        int rh = hs < 49 ? 0 : (hs < 53 ? 1 : 2);
        int rw = wsc < 49 ? 0 : (wsc < 53 ? 1 : 2);
        reg_s[tid] = rh * 3 + rw;
    }
    __syncthreads();

    float accS[4][4];
    #pragma unroll
    for (int ni = 0; ni < 4; ni++)
        #pragma unroll
        for (int c = 0; c < 4; c++) accS[ni][c] = 0.f;

    const int ar = warp_m * 16 + (lane >> 2);
    #pragma unroll
    for (int ks = 0; ks < 4; ks++) {
        const int kc = ks * 8 + (lane & 3);
        float af[4];
        af[0] = q_s[ar][kc];     af[1] = q_s[ar + 8][kc];
        af[2] = q_s[ar][kc + 4]; af[3] = q_s[ar + 8][kc + 4];
        #pragma unroll
        for (int ni = 0; ni < 4; ni++) {
            int bc = warp_n * 32 + ni * 8 + (lane >> 2);
            float bf[2];
            bf[0] = kT[kc][bc];
            bf[1] = kT[kc + 4][bc];
            mma_tf32(accS[ni], af, bf);
        }
    }

    #pragma unroll
    for (int half = 0; half < 2; half++) {
        int i = ar + half * 8;
        int ri = i / 7, ci = i - ri * 7;
        #pragma unroll
        for (int ni = 0; ni < 4; ni++) {
            #pragma unroll
            for (int cj = 0; cj < 2; cj++) {
                int j = warp_n * 32 + ni * 8 + 2 * (lane & 3) + cj;
                float val = accS[ni][half * 2 + cj];
                if (j >= NTOK) {
                    val = -1e30f;
                } else if (i < NTOK) {
                    int rj = j / 7, cjj = j - rj * 7;
                    val += biasH[(ri - rj + 6) * 13 + (ci - cjj + 6)];
                    if (masked && reg_s[i] != reg_s[j]) val -= 100.f;
                }
                S[i][j] = val;
            }
        }
    }
    __syncthreads();

    for (int i = wid; i < NTOK; i += 8) {
        float v1 = S[i][lane];
        float v2 = S[i][lane + 32];
        float m = fmaxf(v1, v2);
        #pragma unroll
        for (int o = 16; o > 0; o >>= 1) m = fmaxf(m, __shfl_xor_sync(0xffffffffu, m, o));
        float e1 = __expf(v1 - m);
        float e2 = __expf(v2 - m);
        float sum = e1 + e2;
        #pragma unroll
        for (int o = 16; o > 0; o >>= 1) sum += __shfl_xor_sync(0xffffffffu, sum, o);
        float inv = 1.f / sum;
        S[i][lane] = e1 * inv;
        S[i][lane + 32] = e2 * inv;
    }
    __syncthreads();

    float accO[2][4];
    #pragma unroll
    for (int ni = 0; ni < 2; ni++)
        #pragma unroll
        for (int c = 0; c < 4; c++) accO[ni][c] = 0.f;

    #pragma unroll
    for (int ks = 0; ks < 8; ks++) {
        const int kc = ks * 8 + (lane & 3);
        float af[4];
        af[0] = S[ar][kc];     af[1] = S[ar + 8][kc];
        af[2] = S[ar][kc + 4]; af[3] = S[ar + 8][kc + 4];
        #pragma unroll
        for (int ni = 0; ni < 2; ni++) {
            int bc = warp_n * 16 + ni * 8 + (lane >> 2);
            float bf[2];
            bf[0] = v_s[kc][bc];
            bf[1] = v_s[kc + 4][bc];
            mma_tf32(accO[ni], af, bf);
        }
    }

    const int outbase = (win * NTOK) * CC + head * DH;
    #pragma unroll
    for (int half = 0; half < 2; half++) {
        int i = ar + half * 8;
        if (i < NTOK) {
            #pragma unroll
            for (int ni = 0; ni < 2; ni++) {
                #pragma unroll
                for (int cj = 0; cj < 2; cj++) {
                    int d = warp_n * 16 + ni * 8 + 2 * (lane & 3) + cj;
                    g_ao[outbase + i * CC + d] = accO[ni][half * 2 + cj];
                }
            }
        }
    }
}

// ---------------------------------------------------------------------------
// Proj GEMM (bf16 tensor) + bias + window-reverse + inv shift + residual
// ---------------------------------------------------------------------------
__global__ __launch_bounds__(256, 2) void proj_kernel(
    const float* __restrict__ x,
    const float* __restrict__ proj_w,
    const float* __restrict__ proj_b,
    float* __restrict__ out)
{
    __shared__ unsigned As[BM][12];
    __shared__ unsigned Bs[8][136];

    const int tid = threadIdx.x;
    const int lane = tid & 31, wid = tid >> 5;
    const int warp_m = wid & 3, warp_n = wid >> 2;
    const int bm = blockIdx.x * BM, bn = blockIdx.y * BN;

    const int r0 = tid >> 2, seg = (tid & 3) * 4;
    const int pB = tid >> 5, nB = (tid & 31) * 4;
    const float* A = g_ao;

    float4 ra0 = *(const float4*)(A + (bm + r0) * CC + seg);
    float4 ra1 = *(const float4*)(A + (bm + r0 + 64) * CC + seg);
    float4 rbl = *(const float4*)(proj_w + (2 * pB) * CC + bn + nB);
    float4 rbh = *(const float4*)(proj_w + (2 * pB + 1) * CC + bn + nB);

    float acc[2][8][4];
    #pragma unroll
    for (int mi = 0; mi < 2; mi++)
        #pragma unroll
        for (int ni = 0; ni < 8; ni++)
            #pragma unroll
            for (int c = 0; c < 4; c++) acc[mi][ni][c] = 0.f;

    for (int k0 = 0; k0 < CC; k0 += BK) {
        As[r0][(seg >> 1)]      = pack_bf16(ra0.x, ra0.y);
        As[r0][(seg >> 1) + 1]  = pack_bf16(ra0.z, ra0.w);
        As[r0 + 64][(seg >> 1)]     = pack_bf16(ra1.x, ra1.y);
        As[r0 + 64][(seg >> 1) + 1] = pack_bf16(ra1.z, ra1.w);
        {
            uint4 bw;
            bw.x = pack_bf16(rbl.x, rbh.x);
            bw.y = pack_bf16(rbl.y, rbh.y);
            bw.z = pack_bf16(rbl.z, rbh.z);
            bw.w = pack_bf16(rbl.w, rbh.w);
            *(uint4*)&Bs[pB][nB] = bw;
        }
        __syncthreads();
        if (k0 + BK < CC) {
            ra0 = *(const float4*)(A + (bm + r0) * CC + k0 + BK + seg);
            ra1 = *(const float4*)(A + (bm + r0 + 64) * CC + k0 + BK + seg);
            rbl = *(const float4*)(proj_w + (k0 + BK + 2 * pB) * CC + bn + nB);
            rbh = *(const float4*)(proj_w + (k0 + BK + 2 * pB + 1) * CC + bn + nB);
        }
        {
            const int p = lane & 3;
            unsigned af[2][4], bf[8][2];
            #pragma unroll
            for (int mi = 0; mi < 2; mi++) {
                int ar = warp_m * 32 + mi * 16 + (lane >> 2);
                af[mi][0] = As[ar][p];     af[mi][1] = As[ar + 8][p];
                af[mi][2] = As[ar][p + 4]; af[mi][3] = As[ar + 8][p + 4];
            }
            #pragma unroll
            for (int ni = 0; ni < 8; ni++) {
                int bc = warp_n * 64 + ni * 8 + (lane >> 2);
                bf[ni][0] = Bs[p][bc];
                bf[ni][1] = Bs[p + 4][bc];
            }
            #pragma unroll
            for (int mi = 0; mi < 2; mi++)
                #pragma unroll
                for (int ni = 0; ni < 8; ni++)
                    mma_bf16(acc[mi][ni], af[mi], bf[ni]);
        }
        __syncthreads();
    }

    #pragma unroll
    for (int mi = 0; mi < 2; mi++) {
        #pragma unroll
        for (int half = 0; half < 2; half++) {
            int m = bm + warp_m * 32 + mi * 16 + (lane >> 2) + half * 8;
            int win = m / NTOK, token = m - win * NTOK;
            int b = win >> 6, widx = win & 63;
            int wh = widx >> 3, ww = widx & 7;
            int th = token / 7, tw = token - th * 7;
            int h = wh * 7 + th + SHIFTV; if (h >= HH)  h -= HH;
            int w = ww * 7 + tw + SHIFTV; if (w >= WWI) w -= WWI;
            int ob = ((b * HH + h) * WWI + w) * CC;
            #pragma unroll
            for (int ni = 0; ni < 8; ni++) {
                #pragma unroll
                for (int cj = 0; cj < 2; cj++) {
                    int n = bn + warp_n * 64 + ni * 8 + 2 * (lane & 3) + cj;
                    out[ob + n] = x[ob + n] + acc[mi][ni][half * 2 + cj] + proj_b[n];
                }
            }
        }
    }
}

extern "C" void kernel_launch(void* const* d_in, const int* in_sizes, int n_in,
                              void* d_out, int out_size)
{
    const float* x          = (const float*)d_in[0];
    const float* qkv_w      = (const float*)d_in[1];
    const float* qkv_b      = (const float*)d_in[2];
    const float* proj_w     = (const float*)d_in[3];
    const float* proj_b     = (const float*)d_in[4];
    const float* bias_table = (const float*)d_in[5];
    float* out = (float*)d_out;

    dim3 g1(MTOT / BM, NQKV / BN);   // 392 x 12
    qkv_kernel<<<g1, 256>>>(x, qkv_w, qkv_b);

    attn_kernel<<<NWIN * NHEADS, 256>>>(bias_table);

    dim3 g3(MTOT / BM, CC / BN);     // 392 x 4
    proj_kernel<<<g3, 256>>>(x, proj_w, proj_b, out);
}

// round 10
// speedup vs baseline: 4.3479x; 1.2872x over previous
#include <cuda_runtime.h>
#include <cuda_bf16.h>

#define BB 16
#define HH 56
#define WWI 56
#define CC 512
#define NHEADS 16
#define DH 32
#define NTOK 49
#define SHIFTV 3
#define NWIN 1024            // B * 64 windows
#define MTOT (NWIN * NTOK)   // 50176
#define NQKV 1536
#define QKV_STRIDE (NWIN * NHEADS * NTOK * DH)
#define XEL (BB * HH * WWI * CC)          // 25690112

// Scratch (device globals; no allocations allowed)
__device__ __nv_bfloat16 g_xb[XEL];               // x in bf16
__device__ __nv_bfloat16 g_wqkv[CC * NQKV];       // qkv_w bf16
__device__ __nv_bfloat16 g_wproj[CC * CC];        // proj_w bf16
__device__ __nv_bfloat16 g_qkvb[3 * QKV_STRIDE];  // [which][win][head][tok][d]
__device__ __nv_bfloat16 g_aob[MTOT * CC];        // attention output bf16

__device__ __forceinline__ unsigned pack_bf16(float lo, float hi) {
    __nv_bfloat162 t = __floats2bfloat162_rn(lo, hi);
    return *(unsigned*)&t;
}
__device__ __forceinline__ unsigned s2u(const void* p) {
    return (unsigned)__cvta_generic_to_shared(p);
}
__device__ __forceinline__ void ldsm4(unsigned* r, unsigned a) {
    asm volatile("ldmatrix.sync.aligned.m8n8.x4.shared.b16 {%0,%1,%2,%3}, [%4];"
        : "=r"(r[0]), "=r"(r[1]), "=r"(r[2]), "=r"(r[3]) : "r"(a));
}
__device__ __forceinline__ void ldsm4t(unsigned* r, unsigned a) {
    asm volatile("ldmatrix.sync.aligned.m8n8.x4.trans.shared.b16 {%0,%1,%2,%3}, [%4];"
        : "=r"(r[0]), "=r"(r[1]), "=r"(r[2]), "=r"(r[3]) : "r"(a));
}

// m16n8k8 tf32 mma (row.col) — attention core
__device__ __forceinline__ void mma_tf32(float* d, const float* a, const float* b) {
    asm volatile(
        "mma.sync.aligned.m16n8k8.row.col.f32.tf32.tf32.f32 "
        "{%0,%1,%2,%3}, {%4,%5,%6,%7}, {%8,%9}, {%0,%1,%2,%3};\n"
        : "+f"(d[0]), "+f"(d[1]), "+f"(d[2]), "+f"(d[3])
        : "r"(__float_as_uint(a[0])), "r"(__float_as_uint(a[1])),
          "r"(__float_as_uint(a[2])), "r"(__float_as_uint(a[3])),
          "r"(__float_as_uint(b[0])), "r"(__float_as_uint(b[1])));
}
// m16n8k16 bf16 mma (row.col) — big GEMMs
__device__ __forceinline__ void mma_bf16(float* d, const unsigned* a, const unsigned* b) {
    asm volatile(
        "mma.sync.aligned.m16n8k16.row.col.f32.bf16.bf16.f32 "
        "{%0,%1,%2,%3}, {%4,%5,%6,%7}, {%8,%9}, {%0,%1,%2,%3};\n"
        : "+f"(d[0]), "+f"(d[1]), "+f"(d[2]), "+f"(d[3])
        : "r"(a[0]), "r"(a[1]), "r"(a[2]), "r"(a[3]),
          "r"(b[0]), "r"(b[1]));
}

// fp32 -> bf16, 8 elements per thread
__global__ __launch_bounds__(256) void cvt8(const float* __restrict__ s,
                                            __nv_bfloat16* __restrict__ d, int n8) {
    int i = blockIdx.x * 256 + threadIdx.x;
    if (i >= n8) return;
    const float4* s4 = (const float4*)s;
    float4 a = s4[2 * i], b = s4[2 * i + 1];
    uint4 o;
    o.x = pack_bf16(a.x, a.y); o.y = pack_bf16(a.z, a.w);
    o.z = pack_bf16(b.x, b.y); o.w = pack_bf16(b.z, b.w);
    ((uint4*)d)[i] = o;
}

// ---------------------------------------------------------------------------
// GEMM v3: 128x128x16 bf16, 256 thr, warps 4x2 (warp 32x64),
// double-buffered smem, ldmatrix fragment loads.
// Ab stride 24 bf16 (48B): ldsm rows 3i mod 8 distinct. Bb stride 136 (272B):
// ldsm rows 17i mod 8 distinct.
// ---------------------------------------------------------------------------
#define BM 128
#define BN 128
#define BK 16
#define NCH (CC / BK)   // 32

struct QkvTag {};  struct ProjTag {};

__global__ __launch_bounds__(256, 2) void qkv_kernel(const float* __restrict__ qkv_b)
{
    __shared__ __nv_bfloat16 Ab[2][BM][24];
    __shared__ __nv_bfloat16 Bb[2][BK][136];
    __shared__ int rowBase[BM];

    const int tid = threadIdx.x;
    const int lane = tid & 31, wid = tid >> 5;
    const int warp_m = wid & 3, warp_n = wid >> 2;
    const int bm = blockIdx.x * BM, bn = blockIdx.y * BN;

    if (tid < BM) {
        int m = bm + tid;
        int win = m / NTOK, token = m - win * NTOK;
        int b = win >> 6, widx = win & 63;
        int wh = widx >> 3, ww = widx & 7;
        int th = token / 7, tw = token - th * 7;
        int h = wh * 7 + th + SHIFTV; if (h >= HH)  h -= HH;
        int w = ww * 7 + tw + SHIFTV; if (w >= WWI) w -= WWI;
        rowBase[tid] = ((b * HH + h) * WWI + w) * CC;
    }
    __syncthreads();

    // A loader: row = tid>>1, half = tid&1 (8 bf16); B loader: k = tid>>4, n0 = (tid&15)*8
    const int arow = tid >> 1, ahalf = (tid & 1) * 8;
    const int rbA = rowBase[arow];
    const int kB = tid >> 4, nB8 = (tid & 15) * 8;

    uint4 a_r = *(const uint4*)(g_xb + rbA + ahalf);
    uint4 b_r = *(const uint4*)(g_wqkv + kB * NQKV + bn + nB8);

    float acc[2][8][4];
    #pragma unroll
    for (int mi = 0; mi < 2; mi++)
        #pragma unroll
        for (int ni = 0; ni < 8; ni++)
            #pragma unroll
            for (int c = 0; c < 4; c++) acc[mi][ni][c] = 0.f;

    *(uint4*)&Ab[0][arow][ahalf] = a_r;
    *(uint4*)&Bb[0][kB][nB8] = b_r;
    __syncthreads();

    const int q = lane >> 3, lr = lane & 7;
    for (int c = 0; c < NCH; c++) {
        const int buf = c & 1;
        if (c + 1 < NCH) {
            a_r = *(const uint4*)(g_xb + rbA + (c + 1) * BK + ahalf);
            b_r = *(const uint4*)(g_wqkv + ((c + 1) * BK + kB) * NQKV + bn + nB8);
        }
        unsigned af[2][4], bf[8][2];
        #pragma unroll
        for (int mi = 0; mi < 2; mi++) {
            int row = warp_m * 32 + mi * 16 + (q & 1) * 8 + lr;
            ldsm4(af[mi], s2u(&Ab[buf][row][(q >> 1) * 8]));
        }
        #pragma unroll
        for (int nj = 0; nj < 4; nj++) {
            unsigned t[4];
            int kk = (q & 1) * 8 + lr;
            int nn = warp_n * 64 + nj * 16 + (q >> 1) * 8;
            ldsm4t(t, s2u(&Bb[buf][kk][nn]));
            bf[2 * nj][0] = t[0]; bf[2 * nj][1] = t[1];
            bf[2 * nj + 1][0] = t[2]; bf[2 * nj + 1][1] = t[3];
        }
        #pragma unroll
        for (int mi = 0; mi < 2; mi++)
            #pragma unroll
            for (int ni = 0; ni < 8; ni++)
                mma_bf16(acc[mi][ni], af[mi], bf[ni]);
        if (c + 1 < NCH) {
            *(uint4*)&Ab[buf ^ 1][arow][ahalf] = a_r;
            *(uint4*)&Bb[buf ^ 1][kB][nB8] = b_r;
        }
        __syncthreads();
    }

    const float scale = 0.17677669529663687f;   // 32^-0.5
    #pragma unroll
    for (int mi = 0; mi < 2; mi++) {
        #pragma unroll
        for (int half = 0; half < 2; half++) {
            int m = bm + warp_m * 32 + mi * 16 + (lane >> 2) + half * 8;
            int win = m / NTOK, token = m - win * NTOK;
            #pragma unroll
            for (int ni = 0; ni < 8; ni++) {
                int n = bn + warp_n * 64 + ni * 8 + 2 * (lane & 3);
                float v0 = acc[mi][ni][half * 2 + 0] + qkv_b[n];
                float v1 = acc[mi][ni][half * 2 + 1] + qkv_b[n + 1];
                int which = n >> 9;
                int head = (n >> 5) & 15;
                int dim = n & 31;
                if (which == 0) { v0 *= scale; v1 *= scale; }
                int idx = which * QKV_STRIDE +
                          ((win * NHEADS + head) * NTOK + token) * DH + dim;
                *(__nv_bfloat162*)&g_qkvb[idx] = __floats2bfloat162_rn(v0, v1);
            }
        }
    }
}

// ---------------------------------------------------------------------------
// Fused attention: tf32 tensor S=QK^T and O=PV, padded 49 -> 64, bf16 I/O.
// ---------------------------------------------------------------------------
#define NP 64

__global__ __launch_bounds__(256) void attn_kernel(const float* __restrict__ bias_table)
{
    __shared__ float q_s[NP][36];
    __shared__ float kT[DH][72];
    __shared__ float v_s[NP][40];
    __shared__ float S[NP][68];
    __shared__ float biasH[169];
    __shared__ int reg_s[NTOK];

    const int tid = threadIdx.x;
    const int lane = tid & 31, wid = tid >> 5;
    const int warp_m = wid & 3, warp_n = wid >> 2;
    const int whid = blockIdx.x;
    const int win = whid >> 4;
    const int head = whid & 15;
    const int base = whid * (NTOK * DH);      // even

    const __nv_bfloat162* qp = (const __nv_bfloat162*)g_qkvb + (base >> 1);
    const __nv_bfloat162* kp = qp + (QKV_STRIDE >> 1);
    const __nv_bfloat162* vp = qp + QKV_STRIDE;

    for (int idx = tid; idx < NTOK * DH / 2; idx += 256) {
        int tok = idx >> 4, dp = (idx & 15) * 2;
        __nv_bfloat162 qv = qp[idx];
        q_s[tok][dp] = __low2float(qv); q_s[tok][dp + 1] = __high2float(qv);
        __nv_bfloat162 kv = kp[idx];
        kT[dp][tok] = __low2float(kv); kT[dp + 1][tok] = __high2float(kv);
        __nv_bfloat162 vv = vp[idx];
        v_s[tok][dp] = __low2float(vv); v_s[tok][dp + 1] = __high2float(vv);
    }
    for (int idx = tid; idx < (NP - NTOK) * DH; idx += 256)
        v_s[NTOK + (idx >> 5)][idx & 31] = 0.f;
    if (tid < 169) biasH[tid] = bias_table[tid * NHEADS + head];

    const int widx = win & 63;
    const int wwh = widx >> 3, www = widx & 7;
    const bool masked = (wwh == 7) || (www == 7);
    if (tid < NTOK) {
        int th = tid / 7, tw = tid - th * 7;
        int hs = wwh * 7 + th, wsc = www * 7 + tw;
        int rh = hs < 49 ? 0 : (hs < 53 ? 1 : 2);
        int rw = wsc < 49 ? 0 : (wsc < 53 ? 1 : 2);
        reg_s[tid] = rh * 3 + rw;
    }
    __syncthreads();

    float accS[4][4];
    #pragma unroll
    for (int ni = 0; ni < 4; ni++)
        #pragma unroll
        for (int c = 0; c < 4; c++) accS[ni][c] = 0.f;

    const int ar = warp_m * 16 + (lane >> 2);
    #pragma unroll
    for (int ks = 0; ks < 4; ks++) {
        const int kc = ks * 8 + (lane & 3);
        float af[4];
        af[0] = q_s[ar][kc];     af[1] = q_s[ar + 8][kc];
        af[2] = q_s[ar][kc + 4]; af[3] = q_s[ar + 8][kc + 4];
        #pragma unroll
        for (int ni = 0; ni < 4; ni++) {
            int bc = warp_n * 32 + ni * 8 + (lane >> 2);
            float bfr[2];
            bfr[0] = kT[kc][bc];
            bfr[1] = kT[kc + 4][bc];
            mma_tf32(accS[ni], af, bfr);
        }
    }

    #pragma unroll
    for (int half = 0; half < 2; half++) {
        int i = ar + half * 8;
        int ri = i / 7, ci = i - ri * 7;
        #pragma unroll
        for (int ni = 0; ni < 4; ni++) {
            #pragma unroll
            for (int cj = 0; cj < 2; cj++) {
                int j = warp_n * 32 + ni * 8 + 2 * (lane & 3) + cj;
                float val = accS[ni][half * 2 + cj];
                if (j >= NTOK) {
                    val = -1e30f;
                } else if (i < NTOK) {
                    int rj = j / 7, cjj = j - rj * 7;
                    val += biasH[(ri - rj + 6) * 13 + (ci - cjj + 6)];
                    if (masked && reg_s[i] != reg_s[j]) val -= 100.f;
                }
                S[i][j] = val;
            }
        }
    }
    __syncthreads();

    for (int i = wid; i < NTOK; i += 8) {
        float v1 = S[i][lane];
        float v2 = S[i][lane + 32];
        float m = fmaxf(v1, v2);
        #pragma unroll
        for (int o = 16; o > 0; o >>= 1) m = fmaxf(m, __shfl_xor_sync(0xffffffffu, m, o));
        float e1 = __expf(v1 - m);
        float e2 = __expf(v2 - m);
        float sum = e1 + e2;
        #pragma unroll
        for (int o = 16; o > 0; o >>= 1) sum += __shfl_xor_sync(0xffffffffu, sum, o);
        float inv = 1.f / sum;
        S[i][lane] = e1 * inv;
        S[i][lane + 32] = e2 * inv;
    }
    __syncthreads();

    float accO[2][4];
    #pragma unroll
    for (int ni = 0; ni < 2; ni++)
        #pragma unroll
        for (int c = 0; c < 4; c++) accO[ni][c] = 0.f;

    #pragma unroll
    for (int ks = 0; ks < 8; ks++) {
        const int kc = ks * 8 + (lane & 3);
        float af[4];
        af[0] = S[ar][kc];     af[1] = S[ar + 8][kc];
        af[2] = S[ar][kc + 4]; af[3] = S[ar + 8][kc + 4];
        #pragma unroll
        for (int ni = 0; ni < 2; ni++) {
            int bc = warp_n * 16 + ni * 8 + (lane >> 2);
            float bfr[2];
            bfr[0] = v_s[kc][bc];
            bfr[1] = v_s[kc + 4][bc];
            mma_tf32(accO[ni], af, bfr);
        }
    }

    const int outbase = (win * NTOK) * CC + head * DH;
    #pragma unroll
    for (int half = 0; half < 2; half++) {
        int i = ar + half * 8;
        if (i < NTOK) {
            #pragma unroll
            for (int ni = 0; ni < 2; ni++) {
                int d = warp_n * 16 + ni * 8 + 2 * (lane & 3);
                *(__nv_bfloat162*)&g_aob[outbase + i * CC + d] =
                    __floats2bfloat162_rn(accO[ni][half * 2 + 0], accO[ni][half * 2 + 1]);
            }
        }
    }
}

// ---------------------------------------------------------------------------
// Proj GEMM v3 (bf16, ldsm, double-buffered) + residual epilogue
// ---------------------------------------------------------------------------
__global__ __launch_bounds__(256, 2) void proj_kernel(
    const float* __restrict__ x,
    const float* __restrict__ proj_b,
    float* __restrict__ out)
{
    __shared__ __nv_bfloat16 Ab[2][BM][24];
    __shared__ __nv_bfloat16 Bb[2][BK][136];

    const int tid = threadIdx.x;
    const int lane = tid & 31, wid = tid >> 5;
    const int warp_m = wid & 3, warp_n = wid >> 2;
    const int bm = blockIdx.x * BM, bn = blockIdx.y * BN;

    const int arow = tid >> 1, ahalf = (tid & 1) * 8;
    const int kB = tid >> 4, nB8 = (tid & 15) * 8;

    uint4 a_r = *(const uint4*)(g_aob + (bm + arow) * CC + ahalf);
    uint4 b_r = *(const uint4*)(g_wproj + kB * CC + bn + nB8);

    float acc[2][8][4];
    #pragma unroll
    for (int mi = 0; mi < 2; mi++)
        #pragma unroll
        for (int ni = 0; ni < 8; ni++)
            #pragma unroll
            for (int c = 0; c < 4; c++) acc[mi][ni][c] = 0.f;

    *(uint4*)&Ab[0][arow][ahalf] = a_r;
    *(uint4*)&Bb[0][kB][nB8] = b_r;
    __syncthreads();

    const int q = lane >> 3, lr = lane & 7;
    for (int c = 0; c < NCH; c++) {
        const int buf = c & 1;
        if (c + 1 < NCH) {
            a_r = *(const uint4*)(g_aob + (bm + arow) * CC + (c + 1) * BK + ahalf);
            b_r = *(const uint4*)(g_wproj + ((c + 1) * BK + kB) * CC + bn + nB8);
        }
        unsigned af[2][4], bf[8][2];
        #pragma unroll
        for (int mi = 0; mi < 2; mi++) {
            int row = warp_m * 32 + mi * 16 + (q & 1) * 8 + lr;
            ldsm4(af[mi], s2u(&Ab[buf][row][(q >> 1) * 8]));
        }
        #pragma unroll
        for (int nj = 0; nj < 4; nj++) {
            unsigned t[4];
            int kk = (q & 1) * 8 + lr;
            int nn = warp_n * 64 + nj * 16 + (q >> 1) * 8;
            ldsm4t(t, s2u(&Bb[buf][kk][nn]));
            bf[2 * nj][0] = t[0]; bf[2 * nj][1] = t[1];
            bf[2 * nj + 1][0] = t[2]; bf[2 * nj + 1][1] = t[3];
        }
        #pragma unroll
        for (int mi = 0; mi < 2; mi++)
            #pragma unroll
            for (int ni = 0; ni < 8; ni++)
                mma_bf16(acc[mi][ni], af[mi], bf[ni]);
        if (c + 1 < NCH) {
            *(uint4*)&Ab[buf ^ 1][arow][ahalf] = a_r;
            *(uint4*)&Bb[buf ^ 1][kB][nB8] = b_r;
        }
        __syncthreads();
    }

    #pragma unroll
    for (int mi = 0; mi < 2; mi++) {
        #pragma unroll
        for (int half = 0; half < 2; half++) {
            int m = bm + warp_m * 32 + mi * 16 + (lane >> 2) + half * 8;
            int win = m / NTOK, token = m - win * NTOK;
            int b = win >> 6, widx = win & 63;
            int wh = widx >> 3, ww = widx & 7;
            int th = token / 7, tw = token - th * 7;
            int h = wh * 7 + th + SHIFTV; if (h >= HH)  h -= HH;
            int w = ww * 7 + tw + SHIFTV; if (w >= WWI) w -= WWI;
            int ob = ((b * HH + h) * WWI + w) * CC;
            #pragma unroll
            for (int ni = 0; ni < 8; ni++) {
                #pragma unroll
                for (int cj = 0; cj < 2; cj++) {
                    int n = bn + warp_n * 64 + ni * 8 + 2 * (lane & 3) + cj;
                    out[ob + n] = x[ob + n] + acc[mi][ni][half * 2 + cj] + proj_b[n];
                }
            }
        }
    }
}

extern "C" void kernel_launch(void* const* d_in, const int* in_sizes, int n_in,
                              void* d_out, int out_size)
{
    const float* x          = (const float*)d_in[0];
    const float* qkv_w      = (const float*)d_in[1];
    const float* qkv_b      = (const float*)d_in[2];
    const float* proj_w     = (const float*)d_in[3];
    const float* proj_b     = (const float*)d_in[4];
    const float* bias_table = (const float*)d_in[5];
    float* out = (float*)d_out;

    __nv_bfloat16 *p_xb, *p_wq, *p_wp;
    cudaGetSymbolAddress((void**)&p_xb, g_xb);
    cudaGetSymbolAddress((void**)&p_wq, g_wqkv);
    cudaGetSymbolAddress((void**)&p_wp, g_wproj);

    cvt8<<<(XEL / 8 + 255) / 256, 256>>>(x, p_xb, XEL / 8);
    cvt8<<<(CC * NQKV / 8 + 255) / 256, 256>>>(qkv_w, p_wq, CC * NQKV / 8);
    cvt8<<<(CC * CC / 8 + 255) / 256, 256>>>(proj_w, p_wp, CC * CC / 8);

    dim3 g1(MTOT / BM, NQKV / BN);   // 392 x 12
    qkv_kernel<<<g1, 256>>>(qkv_b);

    attn_kernel<<<NWIN * NHEADS, 256>>>(bias_table);

    dim3 g3(MTOT / BM, CC / BN);     // 392 x 4
    proj_kernel<<<g3, 256>>>(x, proj_b, out);
}